// round 1
// baseline (speedup 1.0000x reference)
#include <cuda_runtime.h>
#include <cstdint>

// Problem shapes (fixed per metadata)
#define NROWS 16384
#define KDIM  2048
#define MDIM  2048

#define EPSF  1e-6f
#define TINYF 1e-15f

// GEMM tiling
#define BM 128
#define BN 128
#define BK 8
#define TM 8
#define TN 8

typedef unsigned long long u64;

// ---------------- f32x2 packed helpers (Blackwell FFMA2) ----------------
__device__ __forceinline__ u64 pk2(float x, float y) {
    u64 r;
    asm("mov.b64 %0, {%1, %2};" : "=l"(r) : "f"(x), "f"(y));
    return r;
}
__device__ __forceinline__ void fma2(u64 &c, u64 a, u64 b) {
    asm("fma.rn.f32x2 %0, %1, %2, %0;" : "+l"(c) : "l"(a), "l"(b));
}
__device__ __forceinline__ void unpk2(u64 v, float &x, float &y) {
    asm("mov.b64 {%0, %1}, %2;" : "=f"(x), "=f"(y) : "l"(v));
}

// per-row log0 coefficient: asinh(||x_row||)/max(||x_row||, EPS)
__device__ float g_rowcoef[NROWS];

// ---------------- Kernel 1: row coefficients for log0 ----------------
__global__ void log0_coef_kernel(const float* __restrict__ x) {
    int row = blockIdx.x;
    const float4* xr = (const float4*)(x + (size_t)row * KDIM);
    float acc = 0.f;
    for (int j = threadIdx.x; j < KDIM / 4; j += blockDim.x) {
        float4 v = xr[j];
        acc += v.x * v.x + v.y * v.y + v.z * v.z + v.w * v.w;
    }
    #pragma unroll
    for (int o = 16; o; o >>= 1) acc += __shfl_xor_sync(0xffffffffu, acc, o);
    __shared__ float sred[8];
    int wid = threadIdx.x >> 5, lid = threadIdx.x & 31;
    if (lid == 0) sred[wid] = acc;
    __syncthreads();
    if (threadIdx.x == 0) {
        float s = 0.f;
        int nw = blockDim.x >> 5;
        for (int i = 0; i < nw; i++) s += sred[i];
        s = sqrtf(s);
        g_rowcoef[row] = asinhf(s) / fmaxf(s, EPSF);
    }
}

// ---------------- Kernel 2: U = (coef .* X) @ W^T ----------------
// X: [NROWS, KDIM] row-major, W: [MDIM, KDIM] row-major, U: [NROWS, MDIM]
__global__ __launch_bounds__(256, 2)
void gemm_kernel(const float* __restrict__ X, const float* __restrict__ W,
                 float* __restrict__ U) {
    __shared__ __align__(16) float As[BK][BM];
    __shared__ __align__(16) float Bs[BK][BN];

    const int bm = blockIdx.y * BM;   // n-offset (rows of X)
    const int bn = blockIdx.x * BN;   // m-offset (rows of W)
    const int tid = threadIdx.x;
    const int tm = tid >> 4;          // 0..15
    const int tn = tid & 15;          // 0..15

    // cooperative tile loader mapping: 256 threads -> 128 rows x 2 float4
    const int lr  = tid >> 1;         // 0..127
    const int lk4 = (tid & 1) * 4;    // 0 or 4

    const float rc = g_rowcoef[bm + lr];
    const float* Aptr = X + (size_t)(bm + lr) * KDIM + lk4;
    const float* Bptr = W + (size_t)(bn + lr) * KDIM + lk4;

    u64 acc[TM][TN / 2];
    #pragma unroll
    for (int i = 0; i < TM; i++)
        #pragma unroll
        for (int j = 0; j < TN / 2; j++) acc[i][j] = 0ull;

    for (int kt = 0; kt < KDIM; kt += BK) {
        float4 av = *(const float4*)(Aptr + kt);
        float4 bv = *(const float4*)(Bptr + kt);
        av.x *= rc; av.y *= rc; av.z *= rc; av.w *= rc;
        As[lk4 + 0][lr] = av.x; As[lk4 + 1][lr] = av.y;
        As[lk4 + 2][lr] = av.z; As[lk4 + 3][lr] = av.w;
        Bs[lk4 + 0][lr] = bv.x; Bs[lk4 + 1][lr] = bv.y;
        Bs[lk4 + 2][lr] = bv.z; Bs[lk4 + 3][lr] = bv.w;
        __syncthreads();

        #pragma unroll
        for (int k = 0; k < BK; k++) {
            float4 a0 = *(const float4*)&As[k][tm * TM];
            float4 a1 = *(const float4*)&As[k][tm * TM + 4];
            longlong2 bb01 = *(const longlong2*)&Bs[k][tn * TN];
            longlong2 bb23 = *(const longlong2*)&Bs[k][tn * TN + 4];
            u64 bb[4] = { (u64)bb01.x, (u64)bb01.y, (u64)bb23.x, (u64)bb23.y };
            float aa[TM] = { a0.x, a0.y, a0.z, a0.w, a1.x, a1.y, a1.z, a1.w };
            #pragma unroll
            for (int i = 0; i < TM; i++) {
                u64 ap = pk2(aa[i], aa[i]);
                #pragma unroll
                for (int j = 0; j < TN / 2; j++) fma2(acc[i][j], ap, bb[j]);
            }
        }
        __syncthreads();
    }

    #pragma unroll
    for (int i = 0; i < TM; i++) {
        float o[8];
        #pragma unroll
        for (int j = 0; j < TN / 2; j++) unpk2(acc[i][j], o[2 * j], o[2 * j + 1]);
        float4* dst = (float4*)(U + (size_t)(bm + tm * TM + i) * MDIM + bn + tn * TN);
        dst[0] = make_float4(o[0], o[1], o[2], o[3]);
        dst[1] = make_float4(o[4], o[5], o[6], o[7]);
    }
}

// ---------------- Kernel 3: fused epilogue, in-place on U ----------------
// proj_tan0 -> exp0 -> pt_0_to_y -> exp_map (incl. gyro_add), all collapsed
// to out = alpha*u + gamma*b with per-row scalars from {||u||^2, u.b, ||b||^2}.
__global__ void epilogue_kernel(float* __restrict__ U, const float* __restrict__ b) {
    int row = blockIdx.x;
    float* u = U + (size_t)row * MDIM;
    const float4* u4 = (const float4*)u;
    const float4* b4 = (const float4*)b;

    float s_nu2 = 0.f, s_dub = 0.f, s_nb2 = 0.f;
    for (int j = threadIdx.x; j < MDIM / 4; j += blockDim.x) {
        float4 uv = u4[j];
        float4 bv = b4[j];
        s_nu2 += uv.x * uv.x + uv.y * uv.y + uv.z * uv.z + uv.w * uv.w;
        s_dub += uv.x * bv.x + uv.y * bv.y + uv.z * bv.z + uv.w * bv.w;
        s_nb2 += bv.x * bv.x + bv.y * bv.y + bv.z * bv.z + bv.w * bv.w;
    }
    #pragma unroll
    for (int o = 16; o; o >>= 1) {
        s_nu2 += __shfl_xor_sync(0xffffffffu, s_nu2, o);
        s_dub += __shfl_xor_sync(0xffffffffu, s_dub, o);
        s_nb2 += __shfl_xor_sync(0xffffffffu, s_nb2, o);
    }
    __shared__ float sw[8][3];
    __shared__ float fin[3];
    int wid = threadIdx.x >> 5, lid = threadIdx.x & 31;
    if (lid == 0) { sw[wid][0] = s_nu2; sw[wid][1] = s_dub; sw[wid][2] = s_nb2; }
    __syncthreads();
    if (threadIdx.x == 0) {
        float a0 = 0.f, a1 = 0.f, a2 = 0.f;
        int nw = blockDim.x >> 5;
        for (int i = 0; i < nw; i++) { a0 += sw[i][0]; a1 += sw[i][1]; a2 += sw[i][2]; }
        fin[0] = a0; fin[1] = a1; fin[2] = a2;
    }
    __syncthreads();
    const float nu2 = fin[0], dub = fin[1], nb2 = fin[2];

    // ---- scalar chain (all threads redundantly; C = S = 1) ----
    float t     = sqrtf(nu2);
    float r     = fmaxf(t, EPSF);
    float scale = fminf(20.f / r, 1.f);          // proj_tan0
    float ru    = scale * t;
    float coefe = sinhf(ru) / fmaxf(ru, EPSF);   // exp0
    float cy    = coefe * scale;                 // y = cy * u
    float ny2   = cy * cy * nu2;
    float dyb   = cy * dub;
    float bx    = 1.f / fmaxf(sqrtf(1.f + ny2), TINYF);
    float kk    = bx / (1.f + bx);               // pt coef and coef1
    float dxv   = dyb * (1.f + kk * ny2);        // dot(y, bt)
    float nbt2  = nb2 + 2.f * kk * dyb * dyb + kk * kk * dyb * dyb * ny2;
    float gpvv  = fmaxf(nbt2 - dxv * dxv / (1.f + ny2), TINYF);
    float rg    = sqrtf(gpvv);
    float opb   = 1.f + bx;
    float mopb  = fmaxf(opb, TINYF);
    float c2    = -(bx * bx * bx) / (mopb * mopb);
    float lam   = opb / fmaxf(bx, TINYF);
    float z     = fminf(rg, 20.f);               // clip (rg >= 0)
    float sc    = (fabsf(z) < EPSF) ? (1.f + z * z / 6.f)
                                    : (sinhf(z) / fmaxf(z, EPSF));
    float L     = lam * sc;
    float wb    = L * kk;                        // w = wb*b + wy*y
    float wy    = L * (kk * kk * dyb + c2 * dxv);
    float nw2   = wb * wb * nb2 + 2.f * wb * wy * dyb + wy * wy * ny2;
    float dyw   = wb * dyb + wy * ny2;
    float bw    = 1.f / fmaxf(sqrtf(1.f + nw2), TINYF);
    float coefg = kk * dyw + (1.f - bw) / bw;    // gyro_add coef
    float alpha = (1.f + coefg + wy) * cy;       // multiplies u
    float gamma = wb;                            // multiplies b

    float4* uo = (float4*)u;
    for (int j = threadIdx.x; j < MDIM / 4; j += blockDim.x) {
        float4 uv = u4[j];
        float4 bv = b4[j];
        float4 ov;
        ov.x = alpha * uv.x + gamma * bv.x;
        ov.y = alpha * uv.y + gamma * bv.y;
        ov.z = alpha * uv.z + gamma * bv.z;
        ov.w = alpha * uv.w + gamma * bv.w;
        uo[j] = ov;
    }
}

// ---------------- Launch ----------------
extern "C" void kernel_launch(void* const* d_in, const int* in_sizes, int n_in,
                              void* d_out, int out_size) {
    const float* x = (const float*)d_in[0];   // [16384, 2048]
    const float* W = (const float*)d_in[1];   // [2048, 2048]
    const float* b = (const float*)d_in[2];   // [2048]
    float* out = (float*)d_out;               // [16384, 2048]

    log0_coef_kernel<<<NROWS, 256>>>(x);

    dim3 grid(MDIM / BN, NROWS / BM);
    gemm_kernel<<<grid, 256>>>(x, W, out);

    epilogue_kernel<<<NROWS, 256>>>(out, b);
}

// round 3
// speedup vs baseline: 2.5821x; 2.5821x over previous
#include <cuda_runtime.h>
#include <cuda_bf16.h>
#include <cstdint>

typedef unsigned int u32;
typedef unsigned long long u64;

#define NROWS 16384
#define KDIM  2048
#define MDIM  2048
#define EPSF  1e-6f
#define TINYF 1e-15f

// ---- GEMM tiling ----
#define BM 128
#define BN 128
#define BK 32            // bf16 k-elems per stage
#define NIT (KDIM / BK)  // 64
#define ROWB 80          // padded row pitch in bytes (32 bf16 = 64B data + 16B pad)
#define TENSOR_BYTES (128 * ROWB)       // 10240
#define STAGE_BYTES  (4 * TENSOR_BYTES) // 40960: Ahi, Alo, Bhi, Blo
#define NSTAGE 3
#define SMEM_DYN (NSTAGE * STAGE_BYTES) // 122880

// bf16 split scratch (device globals; no allocation allowed)
static __device__ __align__(16) __nv_bfloat16 g_Ahi[(size_t)NROWS * KDIM];
static __device__ __align__(16) __nv_bfloat16 g_Alo[(size_t)NROWS * KDIM];
static __device__ __align__(16) __nv_bfloat16 g_Bhi[(size_t)MDIM * KDIM];
static __device__ __align__(16) __nv_bfloat16 g_Blo[(size_t)MDIM * KDIM];

// ---------------- PTX helpers (sm_80-portable only) ----------------
__device__ __forceinline__ u32 smem_u32(const void* p) {
    u32 a;
    asm("{ .reg .u64 t; cvta.to.shared.u64 t, %1; cvt.u32.u64 %0, t; }"
        : "=r"(a) : "l"(p));
    return a;
}
__device__ __forceinline__ void cp16(u32 dst, const void* src) {
    asm volatile("cp.async.cg.shared.global [%0], [%1], 16;" :: "r"(dst), "l"(src));
}
#define CP_COMMIT()  asm volatile("cp.async.commit_group;" ::: "memory")
#define CP_WAIT1()   asm volatile("cp.async.wait_group 1;" ::: "memory")
#define CP_WAIT0()   asm volatile("cp.async.wait_group 0;" ::: "memory")

__device__ __forceinline__ void ldm4(u32 &r0, u32 &r1, u32 &r2, u32 &r3, u32 addr) {
    asm volatile("ldmatrix.sync.aligned.m8n8.x4.shared.b16 {%0,%1,%2,%3}, [%4];"
                 : "=r"(r0), "=r"(r1), "=r"(r2), "=r"(r3) : "r"(addr));
}
__device__ __forceinline__ void mma_bf16(float* c, u32 a0, u32 a1, u32 a2, u32 a3,
                                         u32 b0, u32 b1) {
    asm volatile(
        "mma.sync.aligned.m16n8k16.row.col.f32.bf16.bf16.f32 "
        "{%0,%1,%2,%3}, {%4,%5,%6,%7}, {%8,%9}, {%0,%1,%2,%3};"
        : "+f"(c[0]), "+f"(c[1]), "+f"(c[2]), "+f"(c[3])
        : "r"(a0), "r"(a1), "r"(a2), "r"(a3), "r"(b0), "r"(b1));
}

// ---------------- Kernel 1: log0 + bf16 split of A ----------------
__global__ void splitA_kernel(const float* __restrict__ x) {
    int row = blockIdx.x, t = threadIdx.x;
    const float4* xr = (const float4*)(x + (size_t)row * KDIM);
    float4 v0 = xr[2 * t], v1 = xr[2 * t + 1];
    float acc = v0.x * v0.x + v0.y * v0.y + v0.z * v0.z + v0.w * v0.w
              + v1.x * v1.x + v1.y * v1.y + v1.z * v1.z + v1.w * v1.w;
    #pragma unroll
    for (int o = 16; o; o >>= 1) acc += __shfl_xor_sync(0xffffffffu, acc, o);
    __shared__ float sred[8];
    __shared__ float s_coef;
    int wid = t >> 5, lid = t & 31;
    if (lid == 0) sred[wid] = acc;
    __syncthreads();
    if (t == 0) {
        float s = 0.f;
        for (int i = 0; i < 8; i++) s += sred[i];
        s = sqrtf(s);
        s_coef = asinhf(s) / fmaxf(s, EPSF);
    }
    __syncthreads();
    float rc = s_coef;
    float in[8] = { v0.x, v0.y, v0.z, v0.w, v1.x, v1.y, v1.z, v1.w };
    __align__(16) __nv_bfloat16 hi[8], lo[8];
    #pragma unroll
    for (int i = 0; i < 8; i++) {
        float v = rc * in[i];
        hi[i] = __float2bfloat16(v);
        lo[i] = __float2bfloat16(v - __bfloat162float(hi[i]));
    }
    size_t o = (size_t)row * KDIM + (size_t)t * 8;
    *(uint4*)(g_Ahi + o) = *(const uint4*)hi;
    *(uint4*)(g_Alo + o) = *(const uint4*)lo;
}

// ---------------- Kernel 2: bf16 split of W ----------------
__global__ void splitB_kernel(const float* __restrict__ W) {
    int row = blockIdx.x, t = threadIdx.x;
    const float4* wr = (const float4*)(W + (size_t)row * KDIM);
    float4 v0 = wr[2 * t], v1 = wr[2 * t + 1];
    float in[8] = { v0.x, v0.y, v0.z, v0.w, v1.x, v1.y, v1.z, v1.w };
    __align__(16) __nv_bfloat16 hi[8], lo[8];
    #pragma unroll
    for (int i = 0; i < 8; i++) {
        hi[i] = __float2bfloat16(in[i]);
        lo[i] = __float2bfloat16(in[i] - __bfloat162float(hi[i]));
    }
    size_t o = (size_t)row * KDIM + (size_t)t * 8;
    *(uint4*)(g_Bhi + o) = *(const uint4*)hi;
    *(uint4*)(g_Blo + o) = *(const uint4*)lo;
}

// ---------------- Kernel 3: mma.sync GEMM  U = Ahi@Bhi^T + Ahi@Blo^T + Alo@Bhi^T ----------------
// smem stage layout: [Ahi 128xROWB][Alo][Bhi][Blo]
__device__ __forceinline__ void load_stage(u32 sbase, int s, int kt, int tid,
                                           size_t arow, size_t brow) {
    u32 base = sbase + (u32)s * STAGE_BYTES;
    const __nv_bfloat16* gsrc[4] = {
        g_Ahi + arow * (size_t)KDIM + kt,
        g_Alo + arow * (size_t)KDIM + kt,
        g_Bhi + brow * (size_t)KDIM + kt,
        g_Blo + brow * (size_t)KDIM + kt
    };
    #pragma unroll
    for (int i = 0; i < 8; i++) {
        // idx in [256*i, 256*i+255] -> tensor = i>>1 (compile-time)
        const int tensor = i >> 1;
        int idx = tid + i * 256;
        int within = idx & 511;
        int r = within >> 2;        // 0..127
        int c = within & 3;         // 0..3 (16B chunks)
        cp16(base + (u32)tensor * TENSOR_BYTES + (u32)r * ROWB + (u32)c * 16,
             gsrc[tensor] + (size_t)r * KDIM + c * 8);
    }
}

__global__ void __launch_bounds__(256, 1)
gemm_kernel(float* __restrict__ U) {
    extern __shared__ __align__(128) char smem[];
    const u32 sbase = smem_u32(smem);
    const int tid = threadIdx.x;
    const int wid = tid >> 5, lane = tid & 31;
    const int wm = wid & 1;          // 2 warp-rows  (64 rows each)
    const int wn = wid >> 1;         // 4 warp-cols  (32 cols each)
    const size_t arow = (size_t)blockIdx.y * BM;
    const size_t brow = (size_t)blockIdx.x * BN;

    // per-thread ldmatrix address components (byte offsets within a tensor)
    const u32 aRow = (u32)(wm * 64 + (lane & 15)) * ROWB + (u32)(lane >> 4) * 16;
    const u32 bRow = (u32)(wn * 32 + ((lane >> 4) << 3) + (lane & 7)) * ROWB
                   + (u32)((lane >> 3) & 1) * 16;

    float acc[4][4][4];
    #pragma unroll
    for (int i = 0; i < 4; i++)
        #pragma unroll
        for (int j = 0; j < 4; j++)
            #pragma unroll
            for (int q = 0; q < 4; q++) acc[i][j][q] = 0.f;

    load_stage(sbase, 0, 0, tid, arow, brow); CP_COMMIT();
    load_stage(sbase, 1, BK, tid, arow, brow); CP_COMMIT();

    for (int it = 0; it < NIT; ++it) {
        if (it == NIT - 1) { CP_WAIT0(); } else { CP_WAIT1(); }
        __syncthreads();
        if (it + 2 < NIT)
            load_stage(sbase, (it + 2) % NSTAGE, (it + 2) * BK, tid, arow, brow);
        CP_COMMIT();

        const u32 tb = sbase + (u32)(it % NSTAGE) * STAGE_BYTES;
        #pragma unroll
        for (int kk = 0; kk < BK; kk += 16) {
            const u32 kb = (u32)kk * 2;
            u32 ah[4][4], al[4][4], bh[4][2], bl[4][2];
            #pragma unroll
            for (int mt = 0; mt < 4; mt++) {
                u32 ad = tb + aRow + (u32)mt * (16 * ROWB) + kb;
                ldm4(ah[mt][0], ah[mt][1], ah[mt][2], ah[mt][3], ad);
                ldm4(al[mt][0], al[mt][1], al[mt][2], al[mt][3], ad + TENSOR_BYTES);
            }
            #pragma unroll
            for (int p = 0; p < 2; p++) {
                u32 bd = tb + 2 * TENSOR_BYTES + bRow + (u32)p * (16 * ROWB) + kb;
                ldm4(bh[2 * p][0], bh[2 * p][1], bh[2 * p + 1][0], bh[2 * p + 1][1], bd);
                ldm4(bl[2 * p][0], bl[2 * p][1], bl[2 * p + 1][0], bl[2 * p + 1][1],
                     bd + TENSOR_BYTES);
            }
            #pragma unroll
            for (int mt = 0; mt < 4; mt++)
                #pragma unroll
                for (int nt = 0; nt < 4; nt++) {
                    mma_bf16(acc[mt][nt], ah[mt][0], ah[mt][1], ah[mt][2], ah[mt][3],
                             bh[nt][0], bh[nt][1]);
                    mma_bf16(acc[mt][nt], ah[mt][0], ah[mt][1], ah[mt][2], ah[mt][3],
                             bl[nt][0], bl[nt][1]);
                    mma_bf16(acc[mt][nt], al[mt][0], al[mt][1], al[mt][2], al[mt][3],
                             bh[nt][0], bh[nt][1]);
                }
        }
    }

    // write accumulators
    const int qr = lane >> 2, qc = lane & 3;
    #pragma unroll
    for (int mt = 0; mt < 4; mt++) {
        size_t r0 = arow + (size_t)(wm * 64 + mt * 16 + qr);
        #pragma unroll
        for (int nt = 0; nt < 4; nt++) {
            float* p = U + r0 * MDIM + brow + (size_t)(wn * 32 + nt * 8 + qc * 2);
            *(float2*)p = make_float2(acc[mt][nt][0], acc[mt][nt][1]);
            *(float2*)(p + 8 * MDIM) = make_float2(acc[mt][nt][2], acc[mt][nt][3]);
        }
    }
}

// ---------------- Kernel 4: fused hyperbolic epilogue (in-place on U) ----------------
__global__ void epilogue_kernel(float* __restrict__ U, const float* __restrict__ b) {
    int row = blockIdx.x;
    float* u = U + (size_t)row * MDIM;
    const float4* u4 = (const float4*)u;
    const float4* b4 = (const float4*)b;

    float s_nu2 = 0.f, s_dub = 0.f, s_nb2 = 0.f;
    for (int j = threadIdx.x; j < MDIM / 4; j += blockDim.x) {
        float4 uv = u4[j];
        float4 bv = b4[j];
        s_nu2 += uv.x * uv.x + uv.y * uv.y + uv.z * uv.z + uv.w * uv.w;
        s_dub += uv.x * bv.x + uv.y * bv.y + uv.z * bv.z + uv.w * bv.w;
        s_nb2 += bv.x * bv.x + bv.y * bv.y + bv.z * bv.z + bv.w * bv.w;
    }
    #pragma unroll
    for (int o = 16; o; o >>= 1) {
        s_nu2 += __shfl_xor_sync(0xffffffffu, s_nu2, o);
        s_dub += __shfl_xor_sync(0xffffffffu, s_dub, o);
        s_nb2 += __shfl_xor_sync(0xffffffffu, s_nb2, o);
    }
    __shared__ float sw[8][3];
    __shared__ float fin[3];
    int wid = threadIdx.x >> 5, lid = threadIdx.x & 31;
    if (lid == 0) { sw[wid][0] = s_nu2; sw[wid][1] = s_dub; sw[wid][2] = s_nb2; }
    __syncthreads();
    if (threadIdx.x == 0) {
        float a0 = 0.f, a1 = 0.f, a2 = 0.f;
        int nw = blockDim.x >> 5;
        for (int i = 0; i < nw; i++) { a0 += sw[i][0]; a1 += sw[i][1]; a2 += sw[i][2]; }
        fin[0] = a0; fin[1] = a1; fin[2] = a2;
    }
    __syncthreads();
    const float nu2 = fin[0], dub = fin[1], nb2 = fin[2];

    float t     = sqrtf(nu2);
    float r     = fmaxf(t, EPSF);
    float scale = fminf(20.f / r, 1.f);          // proj_tan0
    float ru    = scale * t;
    float coefe = sinhf(ru) / fmaxf(ru, EPSF);   // exp0
    float cy    = coefe * scale;                 // y = cy * u
    float ny2   = cy * cy * nu2;
    float dyb   = cy * dub;
    float bx    = 1.f / fmaxf(sqrtf(1.f + ny2), TINYF);
    float kk    = bx / (1.f + bx);
    float dxv   = dyb * (1.f + kk * ny2);
    float nbt2  = nb2 + 2.f * kk * dyb * dyb + kk * kk * dyb * dyb * ny2;
    float gpvv  = fmaxf(nbt2 - dxv * dxv / (1.f + ny2), TINYF);
    float rg    = sqrtf(gpvv);
    float opb   = 1.f + bx;
    float mopb  = fmaxf(opb, TINYF);
    float c2    = -(bx * bx * bx) / (mopb * mopb);
    float lam   = opb / fmaxf(bx, TINYF);
    float z     = fminf(rg, 20.f);
    float sc    = (fabsf(z) < EPSF) ? (1.f + z * z / 6.f)
                                    : (sinhf(z) / fmaxf(z, EPSF));
    float L     = lam * sc;
    float wb    = L * kk;
    float wy    = L * (kk * kk * dyb + c2 * dxv);
    float nw2   = wb * wb * nb2 + 2.f * wb * wy * dyb + wy * wy * ny2;
    float dyw   = wb * dyb + wy * ny2;
    float bw    = 1.f / fmaxf(sqrtf(1.f + nw2), TINYF);
    float coefg = kk * dyw + (1.f - bw) / bw;
    float alpha = (1.f + coefg + wy) * cy;
    float gamma = wb;

    float4* uo = (float4*)u;
    for (int j = threadIdx.x; j < MDIM / 4; j += blockDim.x) {
        float4 uv = u4[j];
        float4 bv = b4[j];
        float4 ov;
        ov.x = alpha * uv.x + gamma * bv.x;
        ov.y = alpha * uv.y + gamma * bv.y;
        ov.z = alpha * uv.z + gamma * bv.z;
        ov.w = alpha * uv.w + gamma * bv.w;
        uo[j] = ov;
    }
}

// ---------------- Launch ----------------
extern "C" void kernel_launch(void* const* d_in, const int* in_sizes, int n_in,
                              void* d_out, int out_size) {
    const float* x = (const float*)d_in[0];   // [16384, 2048]
    const float* W = (const float*)d_in[1];   // [2048, 2048]
    const float* b = (const float*)d_in[2];   // [2048]
    float* out = (float*)d_out;               // [16384, 2048]

    cudaFuncSetAttribute(gemm_kernel, cudaFuncAttributeMaxDynamicSharedMemorySize, SMEM_DYN);

    splitA_kernel<<<NROWS, 256>>>(x);
    splitB_kernel<<<MDIM, 256>>>(W);

    dim3 grid(MDIM / BN, NROWS / BM);         // (16, 128); x-fastest reuses A in L2
    gemm_kernel<<<grid, 256, SMEM_DYN>>>(out);

    epilogue_kernel<<<NROWS, 256>>>(out, b);
}